// round 1
// baseline (speedup 1.0000x reference)
#include <cuda_runtime.h>
#include <math.h>

// ---------------------------------------------------------------------------
// DCRNN encoder: T=32, B=32, N=512, D=H=128, K=2 (num_mat=3), L=2 layers.
//
// Restructuring: gconv is linear in concat([x,h]) -> split into x-part and
// h-part. x-part diffusion + projection for gates AND candidate is
// precomputed for all T in parallel (per layer). Recurrence per step does
// only the h-part: H1=S@H0, H2=2S@H1-H0, fused gate GEMM (+sigmoid, r*h, u),
// RH1=S@RH0, RH2, fused candidate GEMM (+tanh, GRU update, output writes).
//
// Internal layout: [N, B, F] with F contiguous so S-diffusion is a plain
// row-major GEMM [512,512] @ [512, B*F=4096].
// ---------------------------------------------------------------------------

namespace {
constexpr int TT = 32, BB = 32, NN = 512, DD = 128, HH = 128, LL = 2;
constexpr long NBH  = (long)NN * BB * HH;       // 2,097,152
constexpr long TNBH = (long)TT * NBH;           // 67,108,864
constexpr long TNBG = (long)TT * NN * BB * 256; // 134,217,728
}

// Scratch (device-global: no allocation allowed in kernel_launch)
__device__ float g_X0[TNBH];   // layer input, [T,N,B,128]
__device__ float g_Xn[TNBH];   // next-layer input, [T,N,B,128]
__device__ float g_X1[TNBH];
__device__ float g_X2[TNBH];
__device__ float g_GXg[TNBG];  // precomputed gate x-contribution + bg, [T,N,B,256]
__device__ float g_GXc[TNBH];  // precomputed cand x-contribution + bc, [T,N,B,128]
__device__ float g_H0[NBH];
__device__ float g_H1[NBH];
__device__ float g_H2[NBH];
__device__ float g_RH0[NBH];
__device__ float g_RH1[NBH];
__device__ float g_RH2[NBH];
__device__ float g_U[NBH];

// ---------------------------------------------------------------------------
// transpose inputs [T,B,N,D] -> [T,N,B,D] (float4 over D)
__global__ void transpose_in_k(const float4* __restrict__ in, float4* __restrict__ out) {
    long idx = (long)blockIdx.x * blockDim.x + threadIdx.x; // total = T*N*B*32
    int d4 = (int)(idx & 31);
    long r = idx >> 5;
    int b = (int)(r & 31); r >>= 5;
    int n = (int)(r & 511); r >>= 9;
    int t = (int)r;
    out[idx] = in[((((long)t * BB + b) * NN + n) << 5) + d4];
}

// transpose initial hidden [B,N,H] -> [N,B,H]
__global__ void transpose_h_k(const float4* __restrict__ in, float4* __restrict__ out) {
    long idx = (long)blockIdx.x * blockDim.x + threadIdx.x; // total = N*B*32
    int d4 = (int)(idx & 31);
    int b  = (int)((idx >> 5) & 31);
    int n  = (int)(idx >> 10);
    out[idx] = in[(((long)b * NN + n) << 5) + d4];
}

// ---------------------------------------------------------------------------
// Diffusion GEMM: C[z] = alpha * S @ B[z] + beta * Z[z]
// S: [512,512] row-major. B: [512, ncols]. 64x64x16 tile, 256 threads.
__global__ __launch_bounds__(256, 4) void gemm_diff(
    const float* __restrict__ A, const float* __restrict__ Bm,
    float* __restrict__ C, const float* __restrict__ Z,
    float alpha, float beta, int ncols,
    long bStride, long cStride, long zStride)
{
    const float* Bp = Bm + (long)blockIdx.z * bStride;
    float* Cp = C + (long)blockIdx.z * cStride;
    const float* Zp = Z ? Z + (long)blockIdx.z * zStride : nullptr;

    __shared__ float As[16][64];
    __shared__ float Bs[16][64];
    const int tid = threadIdx.x;
    const int tx = tid & 15, ty = tid >> 4;
    const int m0 = blockIdx.y << 6, n0 = blockIdx.x << 6;
    const int ar = tid >> 2, ac = (tid & 3) << 2;
    const int br = tid >> 4, bc = (tid & 15) << 2;
    float acc[4][4] = {};

    for (int k0 = 0; k0 < 512; k0 += 16) {
        float4 av = *(const float4*)(A + (long)(m0 + ar) * 512 + k0 + ac);
        float4 bv = *(const float4*)(Bp + (long)(k0 + br) * ncols + n0 + bc);
        As[ac + 0][ar] = av.x; As[ac + 1][ar] = av.y;
        As[ac + 2][ar] = av.z; As[ac + 3][ar] = av.w;
        *(float4*)(&Bs[br][bc]) = bv;
        __syncthreads();
#pragma unroll
        for (int kk = 0; kk < 16; kk++) {
            float4 a4 = *(const float4*)(&As[kk][ty << 2]);
            float4 b4 = *(const float4*)(&Bs[kk][tx << 2]);
            float aa[4] = {a4.x, a4.y, a4.z, a4.w};
            float bb[4] = {b4.x, b4.y, b4.z, b4.w};
#pragma unroll
            for (int i = 0; i < 4; i++)
#pragma unroll
                for (int j = 0; j < 4; j++) acc[i][j] += aa[i] * bb[j];
        }
        __syncthreads();
    }
#pragma unroll
    for (int i = 0; i < 4; i++) {
        long off = (long)(m0 + (ty << 2) + i) * ncols + n0 + (tx << 2);
        float4 z = Zp ? *(const float4*)(Zp + off) : make_float4(0.f, 0.f, 0.f, 0.f);
        float4 r;
        r.x = alpha * acc[i][0] + beta * z.x;
        r.y = alpha * acc[i][1] + beta * z.y;
        r.z = alpha * acc[i][2] + beta * z.z;
        r.w = alpha * acc[i][3] + beta * z.w;
        *(float4*)(Cp + off) = r;
    }
}

// ---------------------------------------------------------------------------
// Projection GEMM with 3 accumulated K-segments of 128 (the 3 diffusion terms)
// out = f( sum_k A_k @ W_k + pre + bias ), fused epilogues:
//  mode 0: plain (+bias) -> outC  (precompute of GXg / GXc)
//  mode 1: gates: sigmoid; col<128 -> RH0 = r*h ; col>=128 -> U = u
//  mode 2: cand:  c = tanh(v); hn = u*h + (1-u)*c; update H0; scatter outputs
__global__ __launch_bounds__(256, 4) void gemm_proj(
    const float* __restrict__ A0, const float* __restrict__ A1, const float* __restrict__ A2,
    const float* __restrict__ W0, const float* __restrict__ W1, const float* __restrict__ W2,
    int ldw, int nout,
    const float* __restrict__ pre, const float* __restrict__ bias,
    float* __restrict__ outC, int mode,
    const float* __restrict__ h0c, float* __restrict__ rh0, float* __restrict__ uarr,
    float* __restrict__ h0w, float* __restrict__ out_nbh, float* __restrict__ out_bnh,
    float* __restrict__ finp, int t)
{
    __shared__ float As[16][64];
    __shared__ float Ws[16][64];
    const int tid = threadIdx.x;
    const int tx = tid & 15, ty = tid >> 4;
    const int m0 = blockIdx.y << 6, n0 = blockIdx.x << 6;
    const int ar = tid >> 2, ac = (tid & 3) << 2;
    const int br = tid >> 4, bc = (tid & 15) << 2;
    float acc[4][4] = {};

    const float* Aseg[3] = {A0, A1, A2};
    const float* Wseg[3] = {W0, W1, W2};
#pragma unroll
    for (int seg = 0; seg < 3; seg++) {
        const float* Ap = Aseg[seg];
        const float* Wp = Wseg[seg];
        for (int k0 = 0; k0 < 128; k0 += 16) {
            float4 av = *(const float4*)(Ap + (long)(m0 + ar) * 128 + k0 + ac);
            float4 wv = *(const float4*)(Wp + (long)(k0 + br) * ldw + n0 + bc);
            As[ac + 0][ar] = av.x; As[ac + 1][ar] = av.y;
            As[ac + 2][ar] = av.z; As[ac + 3][ar] = av.w;
            *(float4*)(&Ws[br][bc]) = wv;
            __syncthreads();
#pragma unroll
            for (int kk = 0; kk < 16; kk++) {
                float4 a4 = *(const float4*)(&As[kk][ty << 2]);
                float4 b4 = *(const float4*)(&Ws[kk][tx << 2]);
                float aa[4] = {a4.x, a4.y, a4.z, a4.w};
                float bb[4] = {b4.x, b4.y, b4.z, b4.w};
#pragma unroll
                for (int i = 0; i < 4; i++)
#pragma unroll
                    for (int j = 0; j < 4; j++) acc[i][j] += aa[i] * bb[j];
            }
            __syncthreads();
        }
    }

#pragma unroll
    for (int i = 0; i < 4; i++) {
        int m = m0 + (ty << 2) + i;
#pragma unroll
        for (int j = 0; j < 4; j++) {
            int n = n0 + (tx << 2) + j;
            float v = acc[i][j];
            if (mode == 0) {
                if (bias) v += bias[n];
                outC[(long)m * nout + n] = v;
            } else if (mode == 1) {
                v += pre[(long)m * 256 + n];
                float g = 1.f / (1.f + expf(-v));
                if (n < 128) rh0[(long)m * 128 + n] = g * h0c[(long)m * 128 + n];
                else         uarr[(long)m * 128 + (n - 128)] = g;
            } else {
                v += pre[(long)m * 128 + n];
                float c = tanhf(v);
                long o = (long)m * 128 + n;
                float uu = uarr[o];
                float hv = h0c[o];
                float hn = uu * hv + (1.f - uu) * c;
                h0w[o] = hn;
                if (out_nbh) out_nbh[o] = hn;                      // next-layer input [N,B,H]
                int nn = m >> 5, bb2 = m & 31;
                if (out_bnh)                                        // final outputs [T,B,N,H]
                    out_bnh[(((long)t * BB + bb2) * NN + nn) * HH + n] = hn;
                if (finp)                                           // finals [B,N,H] slice
                    finp[((long)bb2 * NN + nn) * HH + n] = hn;
            }
        }
    }
}

// ---------------------------------------------------------------------------
extern "C" void kernel_launch(void* const* d_in, const int* in_sizes, int n_in,
                              void* d_out, int out_size) {
    (void)in_sizes; (void)n_in; (void)out_size;
    const float* inputs = (const float*)d_in[0]; // [T,B,N,D]
    const float* ih     = (const float*)d_in[1]; // [L,B,N,H]
    const float* S      = (const float*)d_in[2]; // [1,N,N]
    const float* Wg     = (const float*)d_in[3]; // [L,768,256]
    const float* bg     = (const float*)d_in[4]; // [L,256]
    const float* Wc     = (const float*)d_in[5]; // [L,768,128]
    const float* bc     = (const float*)d_in[6]; // [L,128]
    float* fin    = (float*)d_out;                       // [L,B,N,H]
    float* outcur = fin + (long)LL * BB * NN * HH;       // [T,B,N,H]

    float *pX0, *pXn, *pX1, *pX2, *pGXg, *pGXc;
    float *pH0, *pH1, *pH2, *pRH0, *pRH1, *pRH2, *pU;
    cudaGetSymbolAddress((void**)&pX0, g_X0);
    cudaGetSymbolAddress((void**)&pXn, g_Xn);
    cudaGetSymbolAddress((void**)&pX1, g_X1);
    cudaGetSymbolAddress((void**)&pX2, g_X2);
    cudaGetSymbolAddress((void**)&pGXg, g_GXg);
    cudaGetSymbolAddress((void**)&pGXc, g_GXc);
    cudaGetSymbolAddress((void**)&pH0, g_H0);
    cudaGetSymbolAddress((void**)&pH1, g_H1);
    cudaGetSymbolAddress((void**)&pH2, g_H2);
    cudaGetSymbolAddress((void**)&pRH0, g_RH0);
    cudaGetSymbolAddress((void**)&pRH1, g_RH1);
    cudaGetSymbolAddress((void**)&pRH2, g_RH2);
    cudaGetSymbolAddress((void**)&pU, g_U);

    transpose_in_k<<<65536, 256>>>((const float4*)inputs, (float4*)pX0);

    for (int l = 0; l < LL; l++) {
        const float* Xin = (l == 0) ? pX0 : pXn;
        const float* wgl = Wg + (long)l * 768 * 256;
        const float* wcl = Wc + (long)l * 768 * 128;

        // --- parallel precompute of x-contributions (all T at once) ---
        gemm_diff<<<dim3(64, 8, TT), 256>>>(S, Xin, pX1, nullptr, 1.f, 0.f, 4096, NBH, NBH, 0);
        gemm_diff<<<dim3(64, 8, TT), 256>>>(S, pX1, pX2, Xin, 2.f, -1.f, 4096, NBH, NBH, NBH);
        gemm_proj<<<dim3(4, 8192), 256>>>(Xin, pX1, pX2,
            wgl + (long)(0 * 256) * 256, wgl + (long)(1 * 256) * 256, wgl + (long)(2 * 256) * 256,
            256, 256, nullptr, bg + l * 256, pGXg, 0,
            nullptr, nullptr, nullptr, nullptr, nullptr, nullptr, nullptr, 0);
        gemm_proj<<<dim3(2, 8192), 256>>>(Xin, pX1, pX2,
            wcl + (long)(0 * 256) * 128, wcl + (long)(1 * 256) * 128, wcl + (long)(2 * 256) * 128,
            128, 128, nullptr, bc + l * 128, pGXc, 0,
            nullptr, nullptr, nullptr, nullptr, nullptr, nullptr, nullptr, 0);

        transpose_h_k<<<2048, 256>>>((const float4*)(ih + (long)l * BB * NN * HH), (float4*)pH0);

        // --- sequential recurrence (h-part only) ---
        for (int t = 0; t < TT; t++) {
            gemm_diff<<<dim3(64, 8, 1), 256>>>(S, pH0, pH1, nullptr, 1.f, 0.f, 4096, 0, 0, 0);
            gemm_diff<<<dim3(64, 8, 1), 256>>>(S, pH1, pH2, pH0, 2.f, -1.f, 4096, 0, 0, 0);
            gemm_proj<<<dim3(4, 256), 256>>>(pH0, pH1, pH2,
                wgl + (long)(0 * 256 + 128) * 256, wgl + (long)(1 * 256 + 128) * 256,
                wgl + (long)(2 * 256 + 128) * 256,
                256, 256, pGXg + (long)t * NN * BB * 256, nullptr, nullptr, 1,
                pH0, pRH0, pU, nullptr, nullptr, nullptr, nullptr, 0);
            gemm_diff<<<dim3(64, 8, 1), 256>>>(S, pRH0, pRH1, nullptr, 1.f, 0.f, 4096, 0, 0, 0);
            gemm_diff<<<dim3(64, 8, 1), 256>>>(S, pRH1, pRH2, pRH0, 2.f, -1.f, 4096, 0, 0, 0);
            gemm_proj<<<dim3(2, 256), 256>>>(pRH0, pRH1, pRH2,
                wcl + (long)(0 * 256 + 128) * 128, wcl + (long)(1 * 256 + 128) * 128,
                wcl + (long)(2 * 256 + 128) * 128,
                128, 128, pGXc + (long)t * NN * BB * 128, nullptr, nullptr, 2,
                pH0, nullptr, pU, pH0,
                (l == 0) ? (pXn + (long)t * NBH) : nullptr,
                (l == 1) ? outcur : nullptr,
                (t == TT - 1) ? (fin + (long)l * BB * NN * HH) : nullptr, t);
        }
    }
}

// round 2
// speedup vs baseline: 2.3727x; 2.3727x over previous
#include <cuda_runtime.h>
#include <math.h>
#include <stdint.h>

// ---------------------------------------------------------------------------
// DCRNN encoder, TF32 tensor-core version (mma.sync m16n8k8).
// T=32, B=32, N=512, D=H=128, K=2 (num_mat=3), L=2.
// Same restructuring as round 1: x-contributions precomputed for all T in
// parallel; sequential recurrence does only h-part (4 diffusion GEMMs + 2
// fused projections per step).
// Layout [N, B, F]: diffusion = S[512,512] @ X[512,4096]; projection views the
// same buffer as [N*B, 128] K-major rows. Weights pre-transposed to [O, F].
// ---------------------------------------------------------------------------

namespace {
constexpr int TT = 32, BB = 32, NN = 512, HH = 128, LL = 2;
constexpr long NBH  = (long)NN * BB * HH;       // 2,097,152
constexpr long TNBH = (long)TT * NBH;
constexpr long TNBG = (long)TT * NN * BB * 256;
}

// Scratch
__device__ float g_X0[TNBH];
__device__ float g_Xn[TNBH];
__device__ float g_X1[TNBH];
__device__ float g_X2[TNBH];
__device__ float g_GXg[TNBG];
__device__ float g_GXc[TNBH];
__device__ float g_H0[NBH];
__device__ float g_H1[NBH];
__device__ float g_H2[NBH];
__device__ float g_RH0[NBH];
__device__ float g_RH1[NBH];
__device__ float g_RH2[NBH];
__device__ float g_U[NBH];
__device__ float g_WgT[(long)LL * 256 * 768];   // [L][256][768]
__device__ float g_WcT[(long)LL * 128 * 768];   // [L][128][768]

// ---------------------------------------------------------------------------
__device__ __forceinline__ float tf32r(float x) {
    uint32_t u; asm("cvt.rna.tf32.f32 %0, %1;" : "=r"(u) : "f"(x));
    return __uint_as_float(u);
}

__device__ __forceinline__ void mma_tf32(float* d, const uint32_t* a, const uint32_t* b) {
    asm volatile(
        "mma.sync.aligned.m16n8k8.row.col.f32.tf32.tf32.f32 "
        "{%0,%1,%2,%3}, {%4,%5,%6,%7}, {%8,%9}, {%0,%1,%2,%3};\n"
        : "+f"(d[0]), "+f"(d[1]), "+f"(d[2]), "+f"(d[3])
        : "r"(a[0]), "r"(a[1]), "r"(a[2]), "r"(a[3]), "r"(b[0]), "r"(b[1]));
}

// ---------------------------------------------------------------------------
// transpose inputs [T,B,N,D] -> [T,N,B,D]
__global__ void transpose_in_k(const float4* __restrict__ in, float4* __restrict__ out) {
    long idx = (long)blockIdx.x * blockDim.x + threadIdx.x;
    int d4 = (int)(idx & 31);
    long rr = idx >> 5;
    int b = (int)(rr & 31); rr >>= 5;
    int n = (int)(rr & 511); rr >>= 9;
    int t = (int)rr;
    out[idx] = in[((((long)t * BB + b) * NN + n) << 5) + d4];
}

// transpose initial hidden [B,N,H] -> [N,B,H]
__global__ void transpose_h_k(const float4* __restrict__ in, float4* __restrict__ out) {
    long idx = (long)blockIdx.x * blockDim.x + threadIdx.x;
    int d4 = (int)(idx & 31);
    int b  = (int)((idx >> 5) & 31);
    int n  = (int)(idx >> 10);
    out[idx] = in[(((long)b * NN + n) << 5) + d4];
}

// W [768, O] -> WT [O, 768]
__global__ void transpose_w_k(const float* __restrict__ W, float* __restrict__ WT, int O) {
    int idx = blockIdx.x * blockDim.x + threadIdx.x;
    if (idx >= 768 * O) return;
    int f = idx / O, o = idx % O;
    WT[(long)o * 768 + f] = W[(long)f * O + o];
}

// ---------------------------------------------------------------------------
// Diffusion GEMM (TF32): C[z] = alpha * S @ B[z] + beta * Z[z]
// S: [512,512] row-major, B: [512, 4096]. CTA tile 128x128x16.
__global__ __launch_bounds__(256, 2) void gemm_diff_t(
    const float* __restrict__ A, const float* __restrict__ Bm,
    float* __restrict__ C, const float* __restrict__ Z,
    float alpha, float beta,
    long bStride, long cStride, long zStride)
{
    constexpr int NC = 4096;
    const float* Bp = Bm + (long)blockIdx.z * bStride;
    float* Cp = C + (long)blockIdx.z * cStride;
    const float* Zp = Z ? Z + (long)blockIdx.z * zStride : nullptr;

    __shared__ float As[16][136];   // [k][m]
    __shared__ float Bs[16][136];   // [k][n]

    const int tid = threadIdx.x;
    const int lane = tid & 31, warp = tid >> 5;
    const int wm0 = (warp & 1) << 6;
    const int wn0 = (warp >> 1) << 5;
    const int r = lane >> 2, c = lane & 3;
    const int m0 = blockIdx.y << 7, n0 = blockIdx.x << 7;

    const int a_row = tid >> 1;            // 0..127
    const int a_q   = (tid & 1) << 3;      // 0 or 8
    const int b_row = tid >> 4;            // 0..15
    const int b_q   = (tid & 15) << 3;     // 0..120 step 8

    float acc[4][4][4] = {};
    float4 ra0, ra1, rb0, rb1;

    auto load_regs = [&](int k0) {
        const float* ap = A + (long)(m0 + a_row) * 512 + k0 + a_q;
        ra0 = *(const float4*)(ap);
        ra1 = *(const float4*)(ap + 4);
        const float* bp = Bp + (long)(k0 + b_row) * NC + n0 + b_q;
        rb0 = *(const float4*)(bp);
        rb1 = *(const float4*)(bp + 4);
    };
    auto store_smem = [&]() {
        As[a_q + 0][a_row] = tf32r(ra0.x); As[a_q + 1][a_row] = tf32r(ra0.y);
        As[a_q + 2][a_row] = tf32r(ra0.z); As[a_q + 3][a_row] = tf32r(ra0.w);
        As[a_q + 4][a_row] = tf32r(ra1.x); As[a_q + 5][a_row] = tf32r(ra1.y);
        As[a_q + 6][a_row] = tf32r(ra1.z); As[a_q + 7][a_row] = tf32r(ra1.w);
        Bs[b_row][b_q + 0] = tf32r(rb0.x); Bs[b_row][b_q + 1] = tf32r(rb0.y);
        Bs[b_row][b_q + 2] = tf32r(rb0.z); Bs[b_row][b_q + 3] = tf32r(rb0.w);
        Bs[b_row][b_q + 4] = tf32r(rb1.x); Bs[b_row][b_q + 5] = tf32r(rb1.y);
        Bs[b_row][b_q + 6] = tf32r(rb1.z); Bs[b_row][b_q + 7] = tf32r(rb1.w);
    };

    load_regs(0); store_smem(); __syncthreads();

    for (int k0 = 0; k0 < 512; k0 += 16) {
        bool more = (k0 + 16 < 512);
        if (more) load_regs(k0 + 16);
#pragma unroll
        for (int kk = 0; kk < 16; kk += 8) {
            uint32_t af[4][4], bf[4][2];
#pragma unroll
            for (int mi = 0; mi < 4; mi++) {
                int mm = wm0 + mi * 16 + r;
                af[mi][0] = __float_as_uint(As[kk + c][mm]);
                af[mi][1] = __float_as_uint(As[kk + c][mm + 8]);
                af[mi][2] = __float_as_uint(As[kk + c + 4][mm]);
                af[mi][3] = __float_as_uint(As[kk + c + 4][mm + 8]);
            }
#pragma unroll
            for (int ni = 0; ni < 4; ni++) {
                int nn = wn0 + ni * 8 + r;
                bf[ni][0] = __float_as_uint(Bs[kk + c][nn]);
                bf[ni][1] = __float_as_uint(Bs[kk + c + 4][nn]);
            }
#pragma unroll
            for (int mi = 0; mi < 4; mi++)
#pragma unroll
                for (int ni = 0; ni < 4; ni++)
                    mma_tf32(acc[mi][ni], af[mi], bf[ni]);
        }
        __syncthreads();
        if (more) { store_smem(); __syncthreads(); }
    }

#pragma unroll
    for (int mi = 0; mi < 4; mi++) {
        int row = m0 + wm0 + mi * 16 + r;
#pragma unroll
        for (int ni = 0; ni < 4; ni++) {
            int col = n0 + wn0 + ni * 8 + 2 * c;
            const float* ap = acc[mi][ni];
            long o0 = (long)row * NC + col;
            long o1 = o0 + 8L * NC;
            float2 out0, out1;
            if (Zp) {
                float2 z0 = *(const float2*)(Zp + o0);
                float2 z1 = *(const float2*)(Zp + o1);
                out0.x = alpha * ap[0] + beta * z0.x;
                out0.y = alpha * ap[1] + beta * z0.y;
                out1.x = alpha * ap[2] + beta * z1.x;
                out1.y = alpha * ap[3] + beta * z1.y;
            } else {
                out0.x = alpha * ap[0]; out0.y = alpha * ap[1];
                out1.x = alpha * ap[2]; out1.y = alpha * ap[3];
            }
            *(float2*)(Cp + o0) = out0;
            *(float2*)(Cp + o1) = out1;
        }
    }
}

// ---------------------------------------------------------------------------
// Projection GEMM (TF32): D = f( sum_seg A_seg @ WT_seg^T + pre + bias )
// A segs: [M,128] rows. WT: [O, 768] row-major; segment s uses cols
// s*256 + xh_off + 0..127. CTA tile 128x128x16.
// modes: 0 plain(+bias)->outC; 1 gates; 2 candidate+GRU update+scatter.
__global__ __launch_bounds__(256, 2) void gemm_proj_t(
    const float* __restrict__ A0, const float* __restrict__ A1, const float* __restrict__ A2,
    const float* __restrict__ WT, int xh_off, int nout,
    const float* __restrict__ pre, const float* __restrict__ bias,
    float* __restrict__ outC, int mode,
    const float* __restrict__ h0c, float* __restrict__ rh0, float* __restrict__ uarr,
    float* __restrict__ h0w, float* __restrict__ out_nbh, float* __restrict__ out_bnh,
    float* __restrict__ finp, int t)
{
    __shared__ float As[16][136];   // [k][m]
    __shared__ float Bs[16][136];   // [k][n]

    const int tid = threadIdx.x;
    const int lane = tid & 31, warp = tid >> 5;
    const int wm0 = (warp & 1) << 6;
    const int wn0 = (warp >> 1) << 5;
    const int r = lane >> 2, c = lane & 3;
    const int m0 = blockIdx.y << 7, n0 = blockIdx.x << 7;

    const int a_row = tid >> 1;            // 0..127 (m)
    const int a_q   = (tid & 1) << 3;      // 0 or 8
    const int b_row = tid >> 1;            // 0..127 (n = WT row)
    const int b_q   = (tid & 1) << 3;      // 0 or 8 (k)

    const float* Aseg[3] = {A0, A1, A2};

    float acc[4][4][4] = {};
    float4 ra0, ra1, rb0, rb1;

    auto load_regs = [&](int k0) {
        int seg = k0 >> 7, within = k0 & 127;
        const float* ap = Aseg[seg] + (long)(m0 + a_row) * 128 + within + a_q;
        ra0 = *(const float4*)(ap);
        ra1 = *(const float4*)(ap + 4);
        const float* bp = WT + (long)(n0 + b_row) * 768 + seg * 256 + xh_off + within + b_q;
        rb0 = *(const float4*)(bp);
        rb1 = *(const float4*)(bp + 4);
    };
    auto store_smem = [&]() {
        As[a_q + 0][a_row] = tf32r(ra0.x); As[a_q + 1][a_row] = tf32r(ra0.y);
        As[a_q + 2][a_row] = tf32r(ra0.z); As[a_q + 3][a_row] = tf32r(ra0.w);
        As[a_q + 4][a_row] = tf32r(ra1.x); As[a_q + 5][a_row] = tf32r(ra1.y);
        As[a_q + 6][a_row] = tf32r(ra1.z); As[a_q + 7][a_row] = tf32r(ra1.w);
        Bs[b_q + 0][b_row] = tf32r(rb0.x); Bs[b_q + 1][b_row] = tf32r(rb0.y);
        Bs[b_q + 2][b_row] = tf32r(rb0.z); Bs[b_q + 3][b_row] = tf32r(rb0.w);
        Bs[b_q + 4][b_row] = tf32r(rb1.x); Bs[b_q + 5][b_row] = tf32r(rb1.y);
        Bs[b_q + 6][b_row] = tf32r(rb1.z); Bs[b_q + 7][b_row] = tf32r(rb1.w);
    };

    load_regs(0); store_smem(); __syncthreads();

    for (int k0 = 0; k0 < 384; k0 += 16) {
        bool more = (k0 + 16 < 384);
        if (more) load_regs(k0 + 16);
#pragma unroll
        for (int kk = 0; kk < 16; kk += 8) {
            uint32_t af[4][4], bf[4][2];
#pragma unroll
            for (int mi = 0; mi < 4; mi++) {
                int mm = wm0 + mi * 16 + r;
                af[mi][0] = __float_as_uint(As[kk + c][mm]);
                af[mi][1] = __float_as_uint(As[kk + c][mm + 8]);
                af[mi][2] = __float_as_uint(As[kk + c + 4][mm]);
                af[mi][3] = __float_as_uint(As[kk + c + 4][mm + 8]);
            }
#pragma unroll
            for (int ni = 0; ni < 4; ni++) {
                int nn = wn0 + ni * 8 + r;
                bf[ni][0] = __float_as_uint(Bs[kk + c][nn]);
                bf[ni][1] = __float_as_uint(Bs[kk + c + 4][nn]);
            }
#pragma unroll
            for (int mi = 0; mi < 4; mi++)
#pragma unroll
                for (int ni = 0; ni < 4; ni++)
                    mma_tf32(acc[mi][ni], af[mi], bf[ni]);
        }
        __syncthreads();
        if (more) { store_smem(); __syncthreads(); }
    }

#pragma unroll
    for (int mi = 0; mi < 4; mi++) {
#pragma unroll
        for (int ni = 0; ni < 4; ni++) {
            const float* ap = acc[mi][ni];
#pragma unroll
            for (int half = 0; half < 2; half++) {
                int row = m0 + wm0 + mi * 16 + r + half * 8;
                float v0 = ap[half * 2 + 0];
                float v1 = ap[half * 2 + 1];
                int col = n0 + wn0 + ni * 8 + 2 * c;
                if (mode == 0) {
                    if (bias) { v0 += bias[col]; v1 += bias[col + 1]; }
                    float2 o; o.x = v0; o.y = v1;
                    *(float2*)(outC + (long)row * nout + col) = o;
                } else if (mode == 1) {
                    const float* pp = pre + (long)row * 256 + col;
                    v0 += pp[0]; v1 += pp[1];
                    float g0 = 1.f / (1.f + __expf(-v0));
                    float g1 = 1.f / (1.f + __expf(-v1));
                    if (col < 128) {
                        long o = (long)row * 128 + col;
                        float2 h = *(const float2*)(h0c + o);
                        float2 out; out.x = g0 * h.x; out.y = g1 * h.y;
                        *(float2*)(rh0 + o) = out;
                    } else {
                        long o = (long)row * 128 + (col - 128);
                        float2 out; out.x = g0; out.y = g1;
                        *(float2*)(uarr + o) = out;
                    }
                } else {
                    long o = (long)row * 128 + col;
                    const float* pp = pre + o;
                    v0 += pp[0]; v1 += pp[1];
                    float c0 = tanhf(v0), c1 = tanhf(v1);
                    float2 uu = *(const float2*)(uarr + o);
                    float2 hh = *(const float2*)(h0c + o);
                    float hn0 = uu.x * hh.x + (1.f - uu.x) * c0;
                    float hn1 = uu.y * hh.y + (1.f - uu.y) * c1;
                    float2 out; out.x = hn0; out.y = hn1;
                    *(float2*)(h0w + o) = out;
                    if (out_nbh) *(float2*)(out_nbh + o) = out;
                    int nn2 = row >> 5, bb2 = row & 31;
                    if (out_bnh)
                        *(float2*)(out_bnh + ((((long)t * BB + bb2) * NN + nn2) * HH + col)) = out;
                    if (finp)
                        *(float2*)(finp + (((long)bb2 * NN + nn2) * HH + col)) = out;
                }
            }
        }
    }
}

// ---------------------------------------------------------------------------
extern "C" void kernel_launch(void* const* d_in, const int* in_sizes, int n_in,
                              void* d_out, int out_size) {
    (void)in_sizes; (void)n_in; (void)out_size;
    const float* inputs = (const float*)d_in[0];
    const float* ih     = (const float*)d_in[1];
    const float* S      = (const float*)d_in[2];
    const float* Wg     = (const float*)d_in[3];
    const float* bg     = (const float*)d_in[4];
    const float* Wc     = (const float*)d_in[5];
    const float* bc     = (const float*)d_in[6];
    float* fin    = (float*)d_out;
    float* outcur = fin + (long)LL * BB * NN * HH;

    float *pX0, *pXn, *pX1, *pX2, *pGXg, *pGXc;
    float *pH0, *pH1, *pH2, *pRH0, *pRH1, *pRH2, *pU, *pWgT, *pWcT;
    cudaGetSymbolAddress((void**)&pX0, g_X0);
    cudaGetSymbolAddress((void**)&pXn, g_Xn);
    cudaGetSymbolAddress((void**)&pX1, g_X1);
    cudaGetSymbolAddress((void**)&pX2, g_X2);
    cudaGetSymbolAddress((void**)&pGXg, g_GXg);
    cudaGetSymbolAddress((void**)&pGXc, g_GXc);
    cudaGetSymbolAddress((void**)&pH0, g_H0);
    cudaGetSymbolAddress((void**)&pH1, g_H1);
    cudaGetSymbolAddress((void**)&pH2, g_H2);
    cudaGetSymbolAddress((void**)&pRH0, g_RH0);
    cudaGetSymbolAddress((void**)&pRH1, g_RH1);
    cudaGetSymbolAddress((void**)&pRH2, g_RH2);
    cudaGetSymbolAddress((void**)&pU, g_U);
    cudaGetSymbolAddress((void**)&pWgT, g_WgT);
    cudaGetSymbolAddress((void**)&pWcT, g_WcT);

    transpose_in_k<<<65536, 256>>>((const float4*)inputs, (float4*)pX0);
    for (int l = 0; l < LL; l++) {
        transpose_w_k<<<768, 256>>>(Wg + (long)l * 768 * 256, pWgT + (long)l * 256 * 768, 256);
        transpose_w_k<<<384, 256>>>(Wc + (long)l * 768 * 128, pWcT + (long)l * 128 * 768, 128);
    }

    for (int l = 0; l < LL; l++) {
        const float* Xin = (l == 0) ? pX0 : pXn;
        const float* wgt = pWgT + (long)l * 256 * 768;
        const float* wct = pWcT + (long)l * 128 * 768;

        // --- parallel precompute of x-contributions (all T at once) ---
        gemm_diff_t<<<dim3(32, 4, TT), 256>>>(S, Xin, pX1, nullptr, 1.f, 0.f, NBH, NBH, 0);
        gemm_diff_t<<<dim3(32, 4, TT), 256>>>(S, pX1, pX2, Xin, 2.f, -1.f, NBH, NBH, NBH);
        gemm_proj_t<<<dim3(2, 4096), 256>>>(Xin, pX1, pX2, wgt, 0, 256,
            nullptr, bg + l * 256, pGXg, 0,
            nullptr, nullptr, nullptr, nullptr, nullptr, nullptr, nullptr, 0);
        gemm_proj_t<<<dim3(1, 4096), 256>>>(Xin, pX1, pX2, wct, 0, 128,
            nullptr, bc + l * 128, pGXc, 0,
            nullptr, nullptr, nullptr, nullptr, nullptr, nullptr, nullptr, 0);

        transpose_h_k<<<2048, 256>>>((const float4*)(ih + (long)l * BB * NN * HH), (float4*)pH0);

        // --- sequential recurrence (h-part only) ---
        for (int t = 0; t < TT; t++) {
            gemm_diff_t<<<dim3(32, 4, 1), 256>>>(S, pH0, pH1, nullptr, 1.f, 0.f, 0, 0, 0);
            gemm_diff_t<<<dim3(32, 4, 1), 256>>>(S, pH1, pH2, pH0, 2.f, -1.f, 0, 0, 0);
            gemm_proj_t<<<dim3(2, 128), 256>>>(pH0, pH1, pH2, wgt, 128, 256,
                pGXg + (long)t * NN * BB * 256, nullptr, nullptr, 1,
                pH0, pRH0, pU, nullptr, nullptr, nullptr, nullptr, 0);
            gemm_diff_t<<<dim3(32, 4, 1), 256>>>(S, pRH0, pRH1, nullptr, 1.f, 0.f, 0, 0, 0);
            gemm_diff_t<<<dim3(32, 4, 1), 256>>>(S, pRH1, pRH2, pRH0, 2.f, -1.f, 0, 0, 0);
            gemm_proj_t<<<dim3(1, 128), 256>>>(pRH0, pRH1, pRH2, wct, 128, 128,
                pGXc + (long)t * NN * BB * 128, nullptr, nullptr, 2,
                pH0, nullptr, pU, pH0,
                (l == 0) ? (pXn + (long)t * NBH) : nullptr,
                (l == 1) ? outcur : nullptr,
                (t == TT - 1) ? (fin + (long)l * BB * NN * HH) : nullptr, t);
        }
    }
}

// round 3
// speedup vs baseline: 2.3733x; 1.0002x over previous
#include <cuda_runtime.h>
#include <math.h>
#include <stdint.h>

// ---------------------------------------------------------------------------
// DCRNN encoder, TF32 tensor-core version (mma.sync m16n8k8).
// T=32, B=32, N=512, D=H=128, K=2 (num_mat=3), L=2.
// Same restructuring as round 1: x-contributions precomputed for all T in
// parallel; sequential recurrence does only h-part (4 diffusion GEMMs + 2
// fused projections per step).
// Layout [N, B, F]: diffusion = S[512,512] @ X[512,4096]; projection views the
// same buffer as [N*B, 128] K-major rows. Weights pre-transposed to [O, F].
// ---------------------------------------------------------------------------

namespace {
constexpr int TT = 32, BB = 32, NN = 512, HH = 128, LL = 2;
constexpr long NBH  = (long)NN * BB * HH;       // 2,097,152
constexpr long TNBH = (long)TT * NBH;
constexpr long TNBG = (long)TT * NN * BB * 256;
}

// Scratch
__device__ float g_X0[TNBH];
__device__ float g_Xn[TNBH];
__device__ float g_X1[TNBH];
__device__ float g_X2[TNBH];
__device__ float g_GXg[TNBG];
__device__ float g_GXc[TNBH];
__device__ float g_H0[NBH];
__device__ float g_H1[NBH];
__device__ float g_H2[NBH];
__device__ float g_RH0[NBH];
__device__ float g_RH1[NBH];
__device__ float g_RH2[NBH];
__device__ float g_U[NBH];
__device__ float g_WgT[(long)LL * 256 * 768];   // [L][256][768]
__device__ float g_WcT[(long)LL * 128 * 768];   // [L][128][768]

// ---------------------------------------------------------------------------
__device__ __forceinline__ float tf32r(float x) {
    uint32_t u; asm("cvt.rna.tf32.f32 %0, %1;" : "=r"(u) : "f"(x));
    return __uint_as_float(u);
}

__device__ __forceinline__ void mma_tf32(float* d, const uint32_t* a, const uint32_t* b) {
    asm volatile(
        "mma.sync.aligned.m16n8k8.row.col.f32.tf32.tf32.f32 "
        "{%0,%1,%2,%3}, {%4,%5,%6,%7}, {%8,%9}, {%0,%1,%2,%3};\n"
        : "+f"(d[0]), "+f"(d[1]), "+f"(d[2]), "+f"(d[3])
        : "r"(a[0]), "r"(a[1]), "r"(a[2]), "r"(a[3]), "r"(b[0]), "r"(b[1]));
}

// ---------------------------------------------------------------------------
// transpose inputs [T,B,N,D] -> [T,N,B,D]
__global__ void transpose_in_k(const float4* __restrict__ in, float4* __restrict__ out) {
    long idx = (long)blockIdx.x * blockDim.x + threadIdx.x;
    int d4 = (int)(idx & 31);
    long rr = idx >> 5;
    int b = (int)(rr & 31); rr >>= 5;
    int n = (int)(rr & 511); rr >>= 9;
    int t = (int)rr;
    out[idx] = in[((((long)t * BB + b) * NN + n) << 5) + d4];
}

// transpose initial hidden [B,N,H] -> [N,B,H]
__global__ void transpose_h_k(const float4* __restrict__ in, float4* __restrict__ out) {
    long idx = (long)blockIdx.x * blockDim.x + threadIdx.x;
    int d4 = (int)(idx & 31);
    int b  = (int)((idx >> 5) & 31);
    int n  = (int)(idx >> 10);
    out[idx] = in[(((long)b * NN + n) << 5) + d4];
}

// W [768, O] -> WT [O, 768]
__global__ void transpose_w_k(const float* __restrict__ W, float* __restrict__ WT, int O) {
    int idx = blockIdx.x * blockDim.x + threadIdx.x;
    if (idx >= 768 * O) return;
    int f = idx / O, o = idx % O;
    WT[(long)o * 768 + f] = W[(long)f * O + o];
}

// ---------------------------------------------------------------------------
// Diffusion GEMM (TF32): C[z] = alpha * S @ B[z] + beta * Z[z]
// S: [512,512] row-major, B: [512, 4096]. CTA tile 128x128x16.
__global__ __launch_bounds__(256, 2) void gemm_diff_t(
    const float* __restrict__ A, const float* __restrict__ Bm,
    float* __restrict__ C, const float* __restrict__ Z,
    float alpha, float beta,
    long bStride, long cStride, long zStride)
{
    constexpr int NC = 4096;
    const float* Bp = Bm + (long)blockIdx.z * bStride;
    float* Cp = C + (long)blockIdx.z * cStride;
    const float* Zp = Z ? Z + (long)blockIdx.z * zStride : nullptr;

    __shared__ float As[16][136];   // [k][m]
    __shared__ float Bs[16][136];   // [k][n]

    const int tid = threadIdx.x;
    const int lane = tid & 31, warp = tid >> 5;
    const int wm0 = (warp & 1) << 6;
    const int wn0 = (warp >> 1) << 5;
    const int r = lane >> 2, c = lane & 3;
    const int m0 = blockIdx.y << 7, n0 = blockIdx.x << 7;

    const int a_row = tid >> 1;            // 0..127
    const int a_q   = (tid & 1) << 3;      // 0 or 8
    const int b_row = tid >> 4;            // 0..15
    const int b_q   = (tid & 15) << 3;     // 0..120 step 8

    float acc[4][4][4] = {};
    float4 ra0, ra1, rb0, rb1;

    auto load_regs = [&](int k0) {
        const float* ap = A + (long)(m0 + a_row) * 512 + k0 + a_q;
        ra0 = *(const float4*)(ap);
        ra1 = *(const float4*)(ap + 4);
        const float* bp = Bp + (long)(k0 + b_row) * NC + n0 + b_q;
        rb0 = *(const float4*)(bp);
        rb1 = *(const float4*)(bp + 4);
    };
    auto store_smem = [&]() {
        As[a_q + 0][a_row] = tf32r(ra0.x); As[a_q + 1][a_row] = tf32r(ra0.y);
        As[a_q + 2][a_row] = tf32r(ra0.z); As[a_q + 3][a_row] = tf32r(ra0.w);
        As[a_q + 4][a_row] = tf32r(ra1.x); As[a_q + 5][a_row] = tf32r(ra1.y);
        As[a_q + 6][a_row] = tf32r(ra1.z); As[a_q + 7][a_row] = tf32r(ra1.w);
        Bs[b_row][b_q + 0] = tf32r(rb0.x); Bs[b_row][b_q + 1] = tf32r(rb0.y);
        Bs[b_row][b_q + 2] = tf32r(rb0.z); Bs[b_row][b_q + 3] = tf32r(rb0.w);
        Bs[b_row][b_q + 4] = tf32r(rb1.x); Bs[b_row][b_q + 5] = tf32r(rb1.y);
        Bs[b_row][b_q + 6] = tf32r(rb1.z); Bs[b_row][b_q + 7] = tf32r(rb1.w);
    };

    load_regs(0); store_smem(); __syncthreads();

    for (int k0 = 0; k0 < 512; k0 += 16) {
        bool more = (k0 + 16 < 512);
        if (more) load_regs(k0 + 16);
#pragma unroll
        for (int kk = 0; kk < 16; kk += 8) {
            uint32_t af[4][4], bf[4][2];
#pragma unroll
            for (int mi = 0; mi < 4; mi++) {
                int mm = wm0 + mi * 16 + r;
                af[mi][0] = __float_as_uint(As[kk + c][mm]);
                af[mi][1] = __float_as_uint(As[kk + c][mm + 8]);
                af[mi][2] = __float_as_uint(As[kk + c + 4][mm]);
                af[mi][3] = __float_as_uint(As[kk + c + 4][mm + 8]);
            }
#pragma unroll
            for (int ni = 0; ni < 4; ni++) {
                int nn = wn0 + ni * 8 + r;
                bf[ni][0] = __float_as_uint(Bs[kk + c][nn]);
                bf[ni][1] = __float_as_uint(Bs[kk + c + 4][nn]);
            }
#pragma unroll
            for (int mi = 0; mi < 4; mi++)
#pragma unroll
                for (int ni = 0; ni < 4; ni++)
                    mma_tf32(acc[mi][ni], af[mi], bf[ni]);
        }
        __syncthreads();
        if (more) { store_smem(); __syncthreads(); }
    }

#pragma unroll
    for (int mi = 0; mi < 4; mi++) {
        int row = m0 + wm0 + mi * 16 + r;
#pragma unroll
        for (int ni = 0; ni < 4; ni++) {
            int col = n0 + wn0 + ni * 8 + 2 * c;
            const float* ap = acc[mi][ni];
            long o0 = (long)row * NC + col;
            long o1 = o0 + 8L * NC;
            float2 out0, out1;
            if (Zp) {
                float2 z0 = *(const float2*)(Zp + o0);
                float2 z1 = *(const float2*)(Zp + o1);
                out0.x = alpha * ap[0] + beta * z0.x;
                out0.y = alpha * ap[1] + beta * z0.y;
                out1.x = alpha * ap[2] + beta * z1.x;
                out1.y = alpha * ap[3] + beta * z1.y;
            } else {
                out0.x = alpha * ap[0]; out0.y = alpha * ap[1];
                out1.x = alpha * ap[2]; out1.y = alpha * ap[3];
            }
            *(float2*)(Cp + o0) = out0;
            *(float2*)(Cp + o1) = out1;
        }
    }
}

// ---------------------------------------------------------------------------
// Projection GEMM (TF32): D = f( sum_seg A_seg @ WT_seg^T + pre + bias )
// A segs: [M,128] rows. WT: [O, 768] row-major; segment s uses cols
// s*256 + xh_off + 0..127. CTA tile 128x128x16.
// modes: 0 plain(+bias)->outC; 1 gates; 2 candidate+GRU update+scatter.
__global__ __launch_bounds__(256, 2) void gemm_proj_t(
    const float* __restrict__ A0, const float* __restrict__ A1, const float* __restrict__ A2,
    const float* __restrict__ WT, int xh_off, int nout,
    const float* __restrict__ pre, const float* __restrict__ bias,
    float* __restrict__ outC, int mode,
    const float* __restrict__ h0c, float* __restrict__ rh0, float* __restrict__ uarr,
    float* __restrict__ h0w, float* __restrict__ out_nbh, float* __restrict__ out_bnh,
    float* __restrict__ finp, int t)
{
    __shared__ float As[16][136];   // [k][m]
    __shared__ float Bs[16][136];   // [k][n]

    const int tid = threadIdx.x;
    const int lane = tid & 31, warp = tid >> 5;
    const int wm0 = (warp & 1) << 6;
    const int wn0 = (warp >> 1) << 5;
    const int r = lane >> 2, c = lane & 3;
    const int m0 = blockIdx.y << 7, n0 = blockIdx.x << 7;

    const int a_row = tid >> 1;            // 0..127 (m)
    const int a_q   = (tid & 1) << 3;      // 0 or 8
    const int b_row = tid >> 1;            // 0..127 (n = WT row)
    const int b_q   = (tid & 1) << 3;      // 0 or 8 (k)

    const float* Aseg[3] = {A0, A1, A2};

    float acc[4][4][4] = {};
    float4 ra0, ra1, rb0, rb1;

    auto load_regs = [&](int k0) {
        int seg = k0 >> 7, within = k0 & 127;
        const float* ap = Aseg[seg] + (long)(m0 + a_row) * 128 + within + a_q;
        ra0 = *(const float4*)(ap);
        ra1 = *(const float4*)(ap + 4);
        const float* bp = WT + (long)(n0 + b_row) * 768 + seg * 256 + xh_off + within + b_q;
        rb0 = *(const float4*)(bp);
        rb1 = *(const float4*)(bp + 4);
    };
    auto store_smem = [&]() {
        As[a_q + 0][a_row] = tf32r(ra0.x); As[a_q + 1][a_row] = tf32r(ra0.y);
        As[a_q + 2][a_row] = tf32r(ra0.z); As[a_q + 3][a_row] = tf32r(ra0.w);
        As[a_q + 4][a_row] = tf32r(ra1.x); As[a_q + 5][a_row] = tf32r(ra1.y);
        As[a_q + 6][a_row] = tf32r(ra1.z); As[a_q + 7][a_row] = tf32r(ra1.w);
        Bs[b_q + 0][b_row] = tf32r(rb0.x); Bs[b_q + 1][b_row] = tf32r(rb0.y);
        Bs[b_q + 2][b_row] = tf32r(rb0.z); Bs[b_q + 3][b_row] = tf32r(rb0.w);
        Bs[b_q + 4][b_row] = tf32r(rb1.x); Bs[b_q + 5][b_row] = tf32r(rb1.y);
        Bs[b_q + 6][b_row] = tf32r(rb1.z); Bs[b_q + 7][b_row] = tf32r(rb1.w);
    };

    load_regs(0); store_smem(); __syncthreads();

    for (int k0 = 0; k0 < 384; k0 += 16) {
        bool more = (k0 + 16 < 384);
        if (more) load_regs(k0 + 16);
#pragma unroll
        for (int kk = 0; kk < 16; kk += 8) {
            uint32_t af[4][4], bf[4][2];
#pragma unroll
            for (int mi = 0; mi < 4; mi++) {
                int mm = wm0 + mi * 16 + r;
                af[mi][0] = __float_as_uint(As[kk + c][mm]);
                af[mi][1] = __float_as_uint(As[kk + c][mm + 8]);
                af[mi][2] = __float_as_uint(As[kk + c + 4][mm]);
                af[mi][3] = __float_as_uint(As[kk + c + 4][mm + 8]);
            }
#pragma unroll
            for (int ni = 0; ni < 4; ni++) {
                int nn = wn0 + ni * 8 + r;
                bf[ni][0] = __float_as_uint(Bs[kk + c][nn]);
                bf[ni][1] = __float_as_uint(Bs[kk + c + 4][nn]);
            }
#pragma unroll
            for (int mi = 0; mi < 4; mi++)
#pragma unroll
                for (int ni = 0; ni < 4; ni++)
                    mma_tf32(acc[mi][ni], af[mi], bf[ni]);
        }
        __syncthreads();
        if (more) { store_smem(); __syncthreads(); }
    }

#pragma unroll
    for (int mi = 0; mi < 4; mi++) {
#pragma unroll
        for (int ni = 0; ni < 4; ni++) {
            const float* ap = acc[mi][ni];
#pragma unroll
            for (int half = 0; half < 2; half++) {
                int row = m0 + wm0 + mi * 16 + r + half * 8;
                float v0 = ap[half * 2 + 0];
                float v1 = ap[half * 2 + 1];
                int col = n0 + wn0 + ni * 8 + 2 * c;
                if (mode == 0) {
                    if (bias) { v0 += bias[col]; v1 += bias[col + 1]; }
                    float2 o; o.x = v0; o.y = v1;
                    *(float2*)(outC + (long)row * nout + col) = o;
                } else if (mode == 1) {
                    const float* pp = pre + (long)row * 256 + col;
                    v0 += pp[0]; v1 += pp[1];
                    float g0 = 1.f / (1.f + __expf(-v0));
                    float g1 = 1.f / (1.f + __expf(-v1));
                    if (col < 128) {
                        long o = (long)row * 128 + col;
                        float2 h = *(const float2*)(h0c + o);
                        float2 out; out.x = g0 * h.x; out.y = g1 * h.y;
                        *(float2*)(rh0 + o) = out;
                    } else {
                        long o = (long)row * 128 + (col - 128);
                        float2 out; out.x = g0; out.y = g1;
                        *(float2*)(uarr + o) = out;
                    }
                } else {
                    long o = (long)row * 128 + col;
                    const float* pp = pre + o;
                    v0 += pp[0]; v1 += pp[1];
                    float c0 = tanhf(v0), c1 = tanhf(v1);
                    float2 uu = *(const float2*)(uarr + o);
                    float2 hh = *(const float2*)(h0c + o);
                    float hn0 = uu.x * hh.x + (1.f - uu.x) * c0;
                    float hn1 = uu.y * hh.y + (1.f - uu.y) * c1;
                    float2 out; out.x = hn0; out.y = hn1;
                    *(float2*)(h0w + o) = out;
                    if (out_nbh) *(float2*)(out_nbh + o) = out;
                    int nn2 = row >> 5, bb2 = row & 31;
                    if (out_bnh)
                        *(float2*)(out_bnh + ((((long)t * BB + bb2) * NN + nn2) * HH + col)) = out;
                    if (finp)
                        *(float2*)(finp + (((long)bb2 * NN + nn2) * HH + col)) = out;
                }
            }
        }
    }
}

// ---------------------------------------------------------------------------
extern "C" void kernel_launch(void* const* d_in, const int* in_sizes, int n_in,
                              void* d_out, int out_size) {
    (void)in_sizes; (void)n_in; (void)out_size;
    const float* inputs = (const float*)d_in[0];
    const float* ih     = (const float*)d_in[1];
    const float* S      = (const float*)d_in[2];
    const float* Wg     = (const float*)d_in[3];
    const float* bg     = (const float*)d_in[4];
    const float* Wc     = (const float*)d_in[5];
    const float* bc     = (const float*)d_in[6];
    float* fin    = (float*)d_out;
    float* outcur = fin + (long)LL * BB * NN * HH;

    float *pX0, *pXn, *pX1, *pX2, *pGXg, *pGXc;
    float *pH0, *pH1, *pH2, *pRH0, *pRH1, *pRH2, *pU, *pWgT, *pWcT;
    cudaGetSymbolAddress((void**)&pX0, g_X0);
    cudaGetSymbolAddress((void**)&pXn, g_Xn);
    cudaGetSymbolAddress((void**)&pX1, g_X1);
    cudaGetSymbolAddress((void**)&pX2, g_X2);
    cudaGetSymbolAddress((void**)&pGXg, g_GXg);
    cudaGetSymbolAddress((void**)&pGXc, g_GXc);
    cudaGetSymbolAddress((void**)&pH0, g_H0);
    cudaGetSymbolAddress((void**)&pH1, g_H1);
    cudaGetSymbolAddress((void**)&pH2, g_H2);
    cudaGetSymbolAddress((void**)&pRH0, g_RH0);
    cudaGetSymbolAddress((void**)&pRH1, g_RH1);
    cudaGetSymbolAddress((void**)&pRH2, g_RH2);
    cudaGetSymbolAddress((void**)&pU, g_U);
    cudaGetSymbolAddress((void**)&pWgT, g_WgT);
    cudaGetSymbolAddress((void**)&pWcT, g_WcT);

    transpose_in_k<<<65536, 256>>>((const float4*)inputs, (float4*)pX0);
    for (int l = 0; l < LL; l++) {
        transpose_w_k<<<768, 256>>>(Wg + (long)l * 768 * 256, pWgT + (long)l * 256 * 768, 256);
        transpose_w_k<<<384, 256>>>(Wc + (long)l * 768 * 128, pWcT + (long)l * 128 * 768, 128);
    }

    for (int l = 0; l < LL; l++) {
        const float* Xin = (l == 0) ? pX0 : pXn;
        const float* wgt = pWgT + (long)l * 256 * 768;
        const float* wct = pWcT + (long)l * 128 * 768;

        // --- parallel precompute of x-contributions (all T at once) ---
        gemm_diff_t<<<dim3(32, 4, TT), 256>>>(S, Xin, pX1, nullptr, 1.f, 0.f, NBH, NBH, 0);
        gemm_diff_t<<<dim3(32, 4, TT), 256>>>(S, pX1, pX2, Xin, 2.f, -1.f, NBH, NBH, NBH);
        gemm_proj_t<<<dim3(2, 4096), 256>>>(Xin, pX1, pX2, wgt, 0, 256,
            nullptr, bg + l * 256, pGXg, 0,
            nullptr, nullptr, nullptr, nullptr, nullptr, nullptr, nullptr, 0);
        gemm_proj_t<<<dim3(1, 4096), 256>>>(Xin, pX1, pX2, wct, 0, 128,
            nullptr, bc + l * 128, pGXc, 0,
            nullptr, nullptr, nullptr, nullptr, nullptr, nullptr, nullptr, 0);

        transpose_h_k<<<2048, 256>>>((const float4*)(ih + (long)l * BB * NN * HH), (float4*)pH0);

        // --- sequential recurrence (h-part only) ---
        for (int t = 0; t < TT; t++) {
            gemm_diff_t<<<dim3(32, 4, 1), 256>>>(S, pH0, pH1, nullptr, 1.f, 0.f, 0, 0, 0);
            gemm_diff_t<<<dim3(32, 4, 1), 256>>>(S, pH1, pH2, pH0, 2.f, -1.f, 0, 0, 0);
            gemm_proj_t<<<dim3(2, 128), 256>>>(pH0, pH1, pH2, wgt, 128, 256,
                pGXg + (long)t * NN * BB * 256, nullptr, nullptr, 1,
                pH0, pRH0, pU, nullptr, nullptr, nullptr, nullptr, 0);
            gemm_diff_t<<<dim3(32, 4, 1), 256>>>(S, pRH0, pRH1, nullptr, 1.f, 0.f, 0, 0, 0);
            gemm_diff_t<<<dim3(32, 4, 1), 256>>>(S, pRH1, pRH2, pRH0, 2.f, -1.f, 0, 0, 0);
            gemm_proj_t<<<dim3(1, 128), 256>>>(pRH0, pRH1, pRH2, wct, 128, 128,
                pGXc + (long)t * NN * BB * 128, nullptr, nullptr, 2,
                pH0, nullptr, pU, pH0,
                (l == 0) ? (pXn + (long)t * NBH) : nullptr,
                (l == 1) ? outcur : nullptr,
                (t == TT - 1) ? (fin + (long)l * BB * NN * HH) : nullptr, t);
        }
    }
}

// round 4
// speedup vs baseline: 2.6108x; 1.1001x over previous
#include <cuda_runtime.h>
#include <math.h>
#include <stdint.h>

// ---------------------------------------------------------------------------
// DCRNN encoder, TF32 mma.sync, Chebyshev-collapsed diffusion.
// T=32, B=32, N=512, D=H=128, K=2 (num_mat=3), L=2.
//
// Key identities:
//   x1 = S@x ; x2 = 2S@x1 - x = (2S^2 - I)@x = M2@x   (M2 precomputed in fp32)
// So the two diffusion terms are INDEPENDENT -> one batched launch.
// Per recurrence step: [S;M2]@H0 -> gate proj -> [S;M2]@RH0 -> cand proj.
// x-contributions (both layers) precomputed for all T in parallel.
// Layout [N, B, F]: diffusion = A[512,512] @ X[512,4096].
// ---------------------------------------------------------------------------

namespace {
constexpr int TT = 32, BB = 32, NN = 512, HH = 128, LL = 2;
constexpr long NBH  = (long)NN * BB * HH;       // 2,097,152
constexpr long TNBH = (long)TT * NBH;
constexpr long TNBG = (long)TT * NN * BB * 256;
}

// Scratch
__device__ float g_X0[TNBH];
__device__ float g_Xn[TNBH];
__device__ float g_X1[TNBH];
__device__ float g_X2[TNBH];
__device__ float g_GXg[TNBG];
__device__ float g_GXc[TNBH];
__device__ float g_H0[NBH];
__device__ float g_H1[NBH];
__device__ float g_H2[NBH];
__device__ float g_RH0[NBH];
__device__ float g_RH1[NBH];
__device__ float g_RH2[NBH];
__device__ float g_U[NBH];
__device__ float g_M2[512 * 512];
__device__ float g_WgT[(long)LL * 256 * 768];   // [L][256][768]
__device__ float g_WcT[(long)LL * 128 * 768];   // [L][128][768]

// ---------------------------------------------------------------------------
__device__ __forceinline__ float tf32r(float x) {
    uint32_t u; asm("cvt.rna.tf32.f32 %0, %1;" : "=r"(u) : "f"(x));
    return __uint_as_float(u);
}

__device__ __forceinline__ void mma_tf32(float* d, const uint32_t* a, const uint32_t* b) {
    asm volatile(
        "mma.sync.aligned.m16n8k8.row.col.f32.tf32.tf32.f32 "
        "{%0,%1,%2,%3}, {%4,%5,%6,%7}, {%8,%9}, {%0,%1,%2,%3};\n"
        : "+f"(d[0]), "+f"(d[1]), "+f"(d[2]), "+f"(d[3])
        : "r"(a[0]), "r"(a[1]), "r"(a[2]), "r"(a[3]), "r"(b[0]), "r"(b[1]));
}

// ---------------------------------------------------------------------------
// M2 = 2*S@S - I, full fp32 (once; 512^3)
__global__ void sq_k(const float* __restrict__ S, float* __restrict__ M2) {
    __shared__ float As[32][33];
    __shared__ float Bs[32][33];
    int tx = threadIdx.x, ty = threadIdx.y;
    int row = (blockIdx.y << 5) + ty, col = (blockIdx.x << 5) + tx;
    float acc = 0.f;
    for (int k0 = 0; k0 < 512; k0 += 32) {
        As[ty][tx] = S[(long)row * 512 + k0 + tx];
        Bs[ty][tx] = S[(long)(k0 + ty) * 512 + col];
        __syncthreads();
#pragma unroll
        for (int kk = 0; kk < 32; kk++) acc += As[ty][kk] * Bs[kk][tx];
        __syncthreads();
    }
    M2[(long)row * 512 + col] = 2.f * acc - (row == col ? 1.f : 0.f);
}

// transpose inputs [T,B,N,D] -> [T,N,B,D]
__global__ void transpose_in_k(const float4* __restrict__ in, float4* __restrict__ out) {
    long idx = (long)blockIdx.x * blockDim.x + threadIdx.x;
    int d4 = (int)(idx & 31);
    long rr = idx >> 5;
    int b = (int)(rr & 31); rr >>= 5;
    int n = (int)(rr & 511); rr >>= 9;
    int t = (int)rr;
    out[idx] = in[((((long)t * BB + b) * NN + n) << 5) + d4];
}

// transpose initial hidden [B,N,H] -> [N,B,H]
__global__ void transpose_h_k(const float4* __restrict__ in, float4* __restrict__ out) {
    long idx = (long)blockIdx.x * blockDim.x + threadIdx.x;
    int d4 = (int)(idx & 31);
    int b  = (int)((idx >> 5) & 31);
    int n  = (int)(idx >> 10);
    out[idx] = in[(((long)b * NN + n) << 5) + d4];
}

// W [768, O] -> WT [O, 768]
__global__ void transpose_w_k(const float* __restrict__ W, float* __restrict__ WT, int O) {
    int idx = blockIdx.x * blockDim.x + threadIdx.x;
    if (idx >= 768 * O) return;
    int f = idx / O, o = idx % O;
    WT[(long)o * 768 + f] = W[(long)f * O + o];
}

// ---------------------------------------------------------------------------
// Batched diffusion GEMM (TF32): for z = 2*pair + which:
//   C_which[pair] = (which ? M2 : S) @ B[pair]
// B: [512, 4096] tiles. CTA tile 128x128x16, 2-stage smem double buffer.
__global__ __launch_bounds__(256, 2) void gemm_diff2(
    const float* __restrict__ Sa, const float* __restrict__ M2a,
    const float* __restrict__ Bbase, long bStride,
    float* __restrict__ C1, float* __restrict__ C2, long cStride)
{
    constexpr int NC = 4096;
    const int pair = blockIdx.z >> 1, which = blockIdx.z & 1;
    const float* A  = which ? M2a : Sa;
    const float* Bp = Bbase + (long)pair * bStride;
    float* Cp = (which ? C2 : C1) + (long)pair * cStride;

    __shared__ float As[2][16][136];   // [stage][k][m]
    __shared__ float Bs[2][16][136];   // [stage][k][n]

    const int tid = threadIdx.x;
    const int lane = tid & 31, warp = tid >> 5;
    const int wm0 = (warp & 1) << 6;
    const int wn0 = (warp >> 1) << 5;
    const int r = lane >> 2, c = lane & 3;
    const int m0 = blockIdx.y << 7, n0 = blockIdx.x << 7;

    const int a_row = tid >> 1;
    const int a_q   = (tid & 1) << 3;
    const int b_row = tid >> 4;
    const int b_q   = (tid & 15) << 3;

    float acc[4][4][4] = {};
    float4 ra0, ra1, rb0, rb1;

    auto load_regs = [&](int k0) {
        const float* ap = A + (long)(m0 + a_row) * 512 + k0 + a_q;
        ra0 = *(const float4*)(ap);
        ra1 = *(const float4*)(ap + 4);
        const float* bp = Bp + (long)(k0 + b_row) * NC + n0 + b_q;
        rb0 = *(const float4*)(bp);
        rb1 = *(const float4*)(bp + 4);
    };
    auto store_smem = [&](int s) {
        As[s][a_q + 0][a_row] = tf32r(ra0.x); As[s][a_q + 1][a_row] = tf32r(ra0.y);
        As[s][a_q + 2][a_row] = tf32r(ra0.z); As[s][a_q + 3][a_row] = tf32r(ra0.w);
        As[s][a_q + 4][a_row] = tf32r(ra1.x); As[s][a_q + 5][a_row] = tf32r(ra1.y);
        As[s][a_q + 6][a_row] = tf32r(ra1.z); As[s][a_q + 7][a_row] = tf32r(ra1.w);
        Bs[s][b_row][b_q + 0] = tf32r(rb0.x); Bs[s][b_row][b_q + 1] = tf32r(rb0.y);
        Bs[s][b_row][b_q + 2] = tf32r(rb0.z); Bs[s][b_row][b_q + 3] = tf32r(rb0.w);
        Bs[s][b_row][b_q + 4] = tf32r(rb1.x); Bs[s][b_row][b_q + 5] = tf32r(rb1.y);
        Bs[s][b_row][b_q + 6] = tf32r(rb1.z); Bs[s][b_row][b_q + 7] = tf32r(rb1.w);
    };

    load_regs(0); store_smem(0); __syncthreads();
    int cur = 0;

    for (int k0 = 0; k0 < 512; k0 += 16) {
        const bool more = (k0 + 16 < 512);
        if (more) load_regs(k0 + 16);
#pragma unroll
        for (int kk = 0; kk < 16; kk += 8) {
            uint32_t af[4][4], bf[4][2];
#pragma unroll
            for (int mi = 0; mi < 4; mi++) {
                int mm = wm0 + mi * 16 + r;
                af[mi][0] = __float_as_uint(As[cur][kk + c][mm]);
                af[mi][1] = __float_as_uint(As[cur][kk + c][mm + 8]);
                af[mi][2] = __float_as_uint(As[cur][kk + c + 4][mm]);
                af[mi][3] = __float_as_uint(As[cur][kk + c + 4][mm + 8]);
            }
#pragma unroll
            for (int ni = 0; ni < 4; ni++) {
                int nn = wn0 + ni * 8 + r;
                bf[ni][0] = __float_as_uint(Bs[cur][kk + c][nn]);
                bf[ni][1] = __float_as_uint(Bs[cur][kk + c + 4][nn]);
            }
#pragma unroll
            for (int mi = 0; mi < 4; mi++)
#pragma unroll
                for (int ni = 0; ni < 4; ni++)
                    mma_tf32(acc[mi][ni], af[mi], bf[ni]);
        }
        if (more) store_smem(cur ^ 1);
        __syncthreads();
        cur ^= 1;
    }

#pragma unroll
    for (int mi = 0; mi < 4; mi++) {
        int row = m0 + wm0 + mi * 16 + r;
#pragma unroll
        for (int ni = 0; ni < 4; ni++) {
            int col = n0 + wn0 + ni * 8 + 2 * c;
            const float* ap = acc[mi][ni];
            long o0 = (long)row * NC + col;
            long o1 = o0 + 8L * NC;
            float2 out0, out1;
            out0.x = ap[0]; out0.y = ap[1];
            out1.x = ap[2]; out1.y = ap[3];
            *(float2*)(Cp + o0) = out0;
            *(float2*)(Cp + o1) = out1;
        }
    }
}

// ---------------------------------------------------------------------------
// Projection GEMM (TF32): D = f( sum_seg A_seg @ WT_seg^T + pre + bias )
// A segs: [M,128] rows. WT: [O, 768] row-major; segment s uses cols
// s*256 + xh_off + 0..127. CTA tile 128x128x16, 2-stage double buffer.
// modes: 0 plain(+bias)->outC; 1 gates; 2 candidate+GRU update+scatter.
__global__ __launch_bounds__(256, 2) void gemm_proj_t(
    const float* __restrict__ A0, const float* __restrict__ A1, const float* __restrict__ A2,
    const float* __restrict__ WT, int xh_off, int nout,
    const float* __restrict__ pre, const float* __restrict__ bias,
    float* __restrict__ outC, int mode,
    const float* __restrict__ h0c, float* __restrict__ rh0, float* __restrict__ uarr,
    float* __restrict__ h0w, float* __restrict__ out_nbh, float* __restrict__ out_bnh,
    float* __restrict__ finp, int t)
{
    __shared__ float As[2][16][136];
    __shared__ float Bs[2][16][136];

    const int tid = threadIdx.x;
    const int lane = tid & 31, warp = tid >> 5;
    const int wm0 = (warp & 1) << 6;
    const int wn0 = (warp >> 1) << 5;
    const int r = lane >> 2, c = lane & 3;
    const int m0 = blockIdx.y << 7, n0 = blockIdx.x << 7;

    const int a_row = tid >> 1;
    const int a_q   = (tid & 1) << 3;
    const int b_row = tid >> 1;
    const int b_q   = (tid & 1) << 3;

    const float* Aseg[3] = {A0, A1, A2};

    float acc[4][4][4] = {};
    float4 ra0, ra1, rb0, rb1;

    auto load_regs = [&](int k0) {
        int seg = k0 >> 7, within = k0 & 127;
        const float* ap = Aseg[seg] + (long)(m0 + a_row) * 128 + within + a_q;
        ra0 = *(const float4*)(ap);
        ra1 = *(const float4*)(ap + 4);
        const float* bp = WT + (long)(n0 + b_row) * 768 + seg * 256 + xh_off + within + b_q;
        rb0 = *(const float4*)(bp);
        rb1 = *(const float4*)(bp + 4);
    };
    auto store_smem = [&](int s) {
        As[s][a_q + 0][a_row] = tf32r(ra0.x); As[s][a_q + 1][a_row] = tf32r(ra0.y);
        As[s][a_q + 2][a_row] = tf32r(ra0.z); As[s][a_q + 3][a_row] = tf32r(ra0.w);
        As[s][a_q + 4][a_row] = tf32r(ra1.x); As[s][a_q + 5][a_row] = tf32r(ra1.y);
        As[s][a_q + 6][a_row] = tf32r(ra1.z); As[s][a_q + 7][a_row] = tf32r(ra1.w);
        Bs[s][b_q + 0][b_row] = tf32r(rb0.x); Bs[s][b_q + 1][b_row] = tf32r(rb0.y);
        Bs[s][b_q + 2][b_row] = tf32r(rb0.z); Bs[s][b_q + 3][b_row] = tf32r(rb0.w);
        Bs[s][b_q + 4][b_row] = tf32r(rb1.x); Bs[s][b_q + 5][b_row] = tf32r(rb1.y);
        Bs[s][b_q + 6][b_row] = tf32r(rb1.z); Bs[s][b_q + 7][b_row] = tf32r(rb1.w);
    };

    load_regs(0); store_smem(0); __syncthreads();
    int cur = 0;

    for (int k0 = 0; k0 < 384; k0 += 16) {
        const bool more = (k0 + 16 < 384);
        if (more) load_regs(k0 + 16);
#pragma unroll
        for (int kk = 0; kk < 16; kk += 8) {
            uint32_t af[4][4], bf[4][2];
#pragma unroll
            for (int mi = 0; mi < 4; mi++) {
                int mm = wm0 + mi * 16 + r;
                af[mi][0] = __float_as_uint(As[cur][kk + c][mm]);
                af[mi][1] = __float_as_uint(As[cur][kk + c][mm + 8]);
                af[mi][2] = __float_as_uint(As[cur][kk + c + 4][mm]);
                af[mi][3] = __float_as_uint(As[cur][kk + c + 4][mm + 8]);
            }
#pragma unroll
            for (int ni = 0; ni < 4; ni++) {
                int nn = wn0 + ni * 8 + r;
                bf[ni][0] = __float_as_uint(Bs[cur][kk + c][nn]);
                bf[ni][1] = __float_as_uint(Bs[cur][kk + c + 4][nn]);
            }
#pragma unroll
            for (int mi = 0; mi < 4; mi++)
#pragma unroll
                for (int ni = 0; ni < 4; ni++)
                    mma_tf32(acc[mi][ni], af[mi], bf[ni]);
        }
        if (more) store_smem(cur ^ 1);
        __syncthreads();
        cur ^= 1;
    }

#pragma unroll
    for (int mi = 0; mi < 4; mi++) {
#pragma unroll
        for (int ni = 0; ni < 4; ni++) {
            const float* ap = acc[mi][ni];
#pragma unroll
            for (int half = 0; half < 2; half++) {
                int row = m0 + wm0 + mi * 16 + r + half * 8;
                float v0 = ap[half * 2 + 0];
                float v1 = ap[half * 2 + 1];
                int col = n0 + wn0 + ni * 8 + 2 * c;
                if (mode == 0) {
                    if (bias) { v0 += bias[col]; v1 += bias[col + 1]; }
                    float2 o; o.x = v0; o.y = v1;
                    *(float2*)(outC + (long)row * nout + col) = o;
                } else if (mode == 1) {
                    const float* pp = pre + (long)row * 256 + col;
                    v0 += pp[0]; v1 += pp[1];
                    float g0 = 1.f / (1.f + __expf(-v0));
                    float g1 = 1.f / (1.f + __expf(-v1));
                    if (col < 128) {
                        long o = (long)row * 128 + col;
                        float2 h = *(const float2*)(h0c + o);
                        float2 out; out.x = g0 * h.x; out.y = g1 * h.y;
                        *(float2*)(rh0 + o) = out;
                    } else {
                        long o = (long)row * 128 + (col - 128);
                        float2 out; out.x = g0; out.y = g1;
                        *(float2*)(uarr + o) = out;
                    }
                } else {
                    long o = (long)row * 128 + col;
                    const float* pp = pre + o;
                    v0 += pp[0]; v1 += pp[1];
                    float c0 = tanhf(v0), c1 = tanhf(v1);
                    float2 uu = *(const float2*)(uarr + o);
                    float2 hh = *(const float2*)(h0c + o);
                    float hn0 = uu.x * hh.x + (1.f - uu.x) * c0;
                    float hn1 = uu.y * hh.y + (1.f - uu.y) * c1;
                    float2 out; out.x = hn0; out.y = hn1;
                    *(float2*)(h0w + o) = out;
                    if (out_nbh) *(float2*)(out_nbh + o) = out;
                    int nn2 = row >> 5, bb2 = row & 31;
                    if (out_bnh)
                        *(float2*)(out_bnh + ((((long)t * BB + bb2) * NN + nn2) * HH + col)) = out;
                    if (finp)
                        *(float2*)(finp + (((long)bb2 * NN + nn2) * HH + col)) = out;
                }
            }
        }
    }
}

// ---------------------------------------------------------------------------
extern "C" void kernel_launch(void* const* d_in, const int* in_sizes, int n_in,
                              void* d_out, int out_size) {
    (void)in_sizes; (void)n_in; (void)out_size;
    const float* inputs = (const float*)d_in[0];
    const float* ih     = (const float*)d_in[1];
    const float* S      = (const float*)d_in[2];
    const float* Wg     = (const float*)d_in[3];
    const float* bg     = (const float*)d_in[4];
    const float* Wc     = (const float*)d_in[5];
    const float* bc     = (const float*)d_in[6];
    float* fin    = (float*)d_out;
    float* outcur = fin + (long)LL * BB * NN * HH;

    float *pX0, *pXn, *pX1, *pX2, *pGXg, *pGXc;
    float *pH0, *pH1, *pH2, *pRH0, *pRH1, *pRH2, *pU, *pM2, *pWgT, *pWcT;
    cudaGetSymbolAddress((void**)&pX0, g_X0);
    cudaGetSymbolAddress((void**)&pXn, g_Xn);
    cudaGetSymbolAddress((void**)&pX1, g_X1);
    cudaGetSymbolAddress((void**)&pX2, g_X2);
    cudaGetSymbolAddress((void**)&pGXg, g_GXg);
    cudaGetSymbolAddress((void**)&pGXc, g_GXc);
    cudaGetSymbolAddress((void**)&pH0, g_H0);
    cudaGetSymbolAddress((void**)&pH1, g_H1);
    cudaGetSymbolAddress((void**)&pH2, g_H2);
    cudaGetSymbolAddress((void**)&pRH0, g_RH0);
    cudaGetSymbolAddress((void**)&pRH1, g_RH1);
    cudaGetSymbolAddress((void**)&pRH2, g_RH2);
    cudaGetSymbolAddress((void**)&pU, g_U);
    cudaGetSymbolAddress((void**)&pM2, g_M2);
    cudaGetSymbolAddress((void**)&pWgT, g_WgT);
    cudaGetSymbolAddress((void**)&pWcT, g_WcT);

    // One-time prep
    sq_k<<<dim3(16, 16), dim3(32, 32)>>>(S, pM2);
    transpose_in_k<<<65536, 256>>>((const float4*)inputs, (float4*)pX0);
    for (int l = 0; l < LL; l++) {
        transpose_w_k<<<768, 256>>>(Wg + (long)l * 768 * 256, pWgT + (long)l * 256 * 768, 256);
        transpose_w_k<<<384, 256>>>(Wc + (long)l * 768 * 128, pWcT + (long)l * 128 * 768, 128);
    }

    for (int l = 0; l < LL; l++) {
        const float* Xin = (l == 0) ? pX0 : pXn;
        const float* wgt = pWgT + (long)l * 256 * 768;
        const float* wct = pWcT + (long)l * 128 * 768;

        // --- parallel precompute of x-contributions (all T, both diffusion terms) ---
        gemm_diff2<<<dim3(32, 4, 2 * TT), 256>>>(S, pM2, Xin, NBH, pX1, pX2, NBH);
        gemm_proj_t<<<dim3(2, 4096), 256>>>(Xin, pX1, pX2, wgt, 0, 256,
            nullptr, bg + l * 256, pGXg, 0,
            nullptr, nullptr, nullptr, nullptr, nullptr, nullptr, nullptr, 0);
        gemm_proj_t<<<dim3(1, 4096), 256>>>(Xin, pX1, pX2, wct, 0, 128,
            nullptr, bc + l * 128, pGXc, 0,
            nullptr, nullptr, nullptr, nullptr, nullptr, nullptr, nullptr, 0);

        transpose_h_k<<<2048, 256>>>((const float4*)(ih + (long)l * BB * NN * HH), (float4*)pH0);

        // --- sequential recurrence: 4 dependent kernels per step ---
        for (int t = 0; t < TT; t++) {
            gemm_diff2<<<dim3(32, 4, 2), 256>>>(S, pM2, pH0, 0, pH1, pH2, 0);
            gemm_proj_t<<<dim3(2, 128), 256>>>(pH0, pH1, pH2, wgt, 128, 256,
                pGXg + (long)t * NN * BB * 256, nullptr, nullptr, 1,
                pH0, pRH0, pU, nullptr, nullptr, nullptr, nullptr, 0);
            gemm_diff2<<<dim3(32, 4, 2), 256>>>(S, pM2, pRH0, 0, pRH1, pRH2, 0);
            gemm_proj_t<<<dim3(1, 128), 256>>>(pRH0, pRH1, pRH2, wct, 128, 128,
                pGXc + (long)t * NN * BB * 128, nullptr, nullptr, 2,
                pH0, nullptr, pU, pH0,
                (l == 0) ? (pXn + (long)t * NBH) : nullptr,
                (l == 1) ? outcur : nullptr,
                (t == TT - 1) ? (fin + (long)l * BB * NN * HH) : nullptr, t);
        }
    }
}